// round 1
// baseline (speedup 1.0000x reference)
#include <cuda_runtime.h>
#include <cuda_bf16.h>
#include <math.h>

// Problem constants
#define BB 16
#define SS 2048
#define DD 512

// ---------------------------------------------------------------------------
// Scratch (device globals — no allocation allowed)
// ---------------------------------------------------------------------------
__device__ float g_q[(size_t)BB * SS * DD];        // 64 MB
__device__ float g_kp[(size_t)BB * SS * DD];       // 64 MB
__device__ float g_vp[(size_t)BB * SS * DD];       // 64 MB
__device__ float g_outpre[(size_t)BB * SS * DD];   // 64 MB
__device__ float g_Wkp[DD * DD];                   // E1 @ Wk
__device__ float g_Wvp[DD * DD];                   // E2 @ Wv
__device__ float g_bkp[DD];
__device__ float g_bvp[DD];

// ---------------------------------------------------------------------------
// SGEMM: C = alpha * A (@) op(B) + bias
//   TRANSB = true : C[m,n] = sum_k A[m,k] * B[n,k]   (x @ W^T form)
//   TRANSB = false: C[m,n] = sum_k A[m,k] * B[k,n]
// 128x128 tile, BK=8, 256 threads, 8x8 per-thread microtile.
// Requires M%128==0, N%128==0, K%8==0 (all shapes here satisfy this).
// Batched via blockIdx.z with element strides.
// ---------------------------------------------------------------------------
template <bool TRANSB>
__global__ __launch_bounds__(256)
void sgemm_kernel(const float* __restrict__ A, const float* __restrict__ Bm,
                  float* __restrict__ C, const float* __restrict__ bias,
                  int M, int N, int K, float alpha,
                  long long strideA, long long strideB, long long strideC)
{
    A  += (long long)blockIdx.z * strideA;
    Bm += (long long)blockIdx.z * strideB;
    C  += (long long)blockIdx.z * strideC;

    const int BM = 128, BN = 128, BK = 8;
    __shared__ float As[BK][BM];
    __shared__ float Bs[BK][BN];

    const int tid = threadIdx.x;          // 0..255
    const int tx = tid & 15;              // 16 col-groups
    const int ty = tid >> 4;              // 16 row-groups
    const int rowBase = blockIdx.y * BM;
    const int colBase = blockIdx.x * BN;

    float acc[8][8];
#pragma unroll
    for (int i = 0; i < 8; i++)
#pragma unroll
        for (int j = 0; j < 8; j++) acc[i][j] = 0.0f;

    for (int k0 = 0; k0 < K; k0 += BK) {
        // Load A tile (128 rows x 8 k), transposed into As[k][m]
        {
            const int r  = tid >> 1;           // 0..127
            const int kc = (tid & 1) * 4;      // 0 or 4
            float4 a = *reinterpret_cast<const float4*>(
                A + (long long)(rowBase + r) * K + k0 + kc);
            As[kc + 0][r] = a.x; As[kc + 1][r] = a.y;
            As[kc + 2][r] = a.z; As[kc + 3][r] = a.w;
        }
        // Load B tile into Bs[k][n]
        if (TRANSB) {
            const int r  = tid >> 1;           // n index 0..127
            const int kc = (tid & 1) * 4;
            float4 b = *reinterpret_cast<const float4*>(
                Bm + (long long)(colBase + r) * K + k0 + kc);
            Bs[kc + 0][r] = b.x; Bs[kc + 1][r] = b.y;
            Bs[kc + 2][r] = b.z; Bs[kc + 3][r] = b.w;
        } else {
            const int kr = tid >> 5;           // 0..7
            const int c  = (tid & 31) * 4;     // 0..124
            float4 b = *reinterpret_cast<const float4*>(
                Bm + (long long)(k0 + kr) * N + colBase + c);
            Bs[kr][c + 0] = b.x; Bs[kr][c + 1] = b.y;
            Bs[kr][c + 2] = b.z; Bs[kr][c + 3] = b.w;
        }
        __syncthreads();

#pragma unroll
        for (int k = 0; k < BK; k++) {
            float4 a0 = *reinterpret_cast<const float4*>(&As[k][ty * 8]);
            float4 a1 = *reinterpret_cast<const float4*>(&As[k][ty * 8 + 4]);
            float4 b0 = *reinterpret_cast<const float4*>(&Bs[k][tx * 8]);
            float4 b1 = *reinterpret_cast<const float4*>(&Bs[k][tx * 8 + 4]);
            float ar[8] = {a0.x, a0.y, a0.z, a0.w, a1.x, a1.y, a1.z, a1.w};
            float br[8] = {b0.x, b0.y, b0.z, b0.w, b1.x, b1.y, b1.z, b1.w};
#pragma unroll
            for (int i = 0; i < 8; i++)
#pragma unroll
                for (int j = 0; j < 8; j++)
                    acc[i][j] = fmaf(ar[i], br[j], acc[i][j]);
        }
        __syncthreads();
    }

    // Epilogue
#pragma unroll
    for (int i = 0; i < 8; i++) {
        const int r = rowBase + ty * 8 + i;
#pragma unroll
        for (int j = 0; j < 8; j += 4) {
            const int c = colBase + tx * 8 + j;
            float4 v;
            v.x = alpha * acc[i][j + 0];
            v.y = alpha * acc[i][j + 1];
            v.z = alpha * acc[i][j + 2];
            v.w = alpha * acc[i][j + 3];
            if (bias) {
                v.x += bias[c + 0]; v.y += bias[c + 1];
                v.z += bias[c + 2]; v.w += bias[c + 3];
            }
            *reinterpret_cast<float4*>(C + (long long)r * N + c) = v;
        }
    }
}

// ---------------------------------------------------------------------------
// Fused bias: out[p] = sum_d E[p,d] * b[d]   (512x512 matvec, tiny)
// ---------------------------------------------------------------------------
__global__ void fuse_bias_kernel(const float* __restrict__ E,
                                 const float* __restrict__ b,
                                 float* __restrict__ out)
{
    const int p = blockIdx.x * blockDim.x + threadIdx.x;
    if (p >= DD) return;
    float s = 0.0f;
    for (int d = 0; d < DD; d++) s = fmaf(E[(long long)p * DD + d], b[d], s);
    out[p] = s;
}

// ---------------------------------------------------------------------------
// Row softmax, row length 2048, in place. One block (256 thr) per row.
// ---------------------------------------------------------------------------
__global__ __launch_bounds__(256)
void softmax2048_kernel(float* __restrict__ data)
{
    float* row = data + (size_t)blockIdx.x * 2048;
    const int tid = threadIdx.x;
    __shared__ float red[8];

    float v[8];
    float m = -3.4e38f;
#pragma unroll
    for (int i = 0; i < 8; i++) {
        v[i] = row[tid + 256 * i];
        m = fmaxf(m, v[i]);
    }
#pragma unroll
    for (int o = 16; o > 0; o >>= 1)
        m = fmaxf(m, __shfl_xor_sync(0xffffffffu, m, o));
    if ((tid & 31) == 0) red[tid >> 5] = m;
    __syncthreads();
    float bm = red[0];
#pragma unroll
    for (int i = 1; i < 8; i++) bm = fmaxf(bm, red[i]);
    __syncthreads();

    float s = 0.0f;
#pragma unroll
    for (int i = 0; i < 8; i++) {
        v[i] = __expf(v[i] - bm);
        s += v[i];
    }
#pragma unroll
    for (int o = 16; o > 0; o >>= 1)
        s += __shfl_xor_sync(0xffffffffu, s, o);
    if ((tid & 31) == 0) red[tid >> 5] = s;
    __syncthreads();
    float bs = 0.0f;
#pragma unroll
    for (int i = 0; i < 8; i++) bs += red[i];

    const float inv = 1.0f / bs;
#pragma unroll
    for (int i = 0; i < 8; i++) row[tid + 256 * i] = v[i] * inv;
}

// ---------------------------------------------------------------------------
// Launch
// ---------------------------------------------------------------------------
extern "C" void kernel_launch(void* const* d_in, const int* in_sizes, int n_in,
                              void* d_out, int out_size)
{
    const float* q_in = (const float*)d_in[0];
    const float* k_in = (const float*)d_in[1];
    const float* v_in = (const float*)d_in[2];
    const float* Wq   = (const float*)d_in[3];
    const float* bq   = (const float*)d_in[4];
    const float* Wk   = (const float*)d_in[5];
    const float* bk   = (const float*)d_in[6];
    const float* Wv   = (const float*)d_in[7];
    const float* bv   = (const float*)d_in[8];
    const float* E1   = (const float*)d_in[9];
    const float* E2   = (const float*)d_in[10];
    const float* Wo   = (const float*)d_in[11];
    const float* bo   = (const float*)d_in[12];

    float* outp = (float*)d_out;                                // [B*S, D]
    float* attn = outp + (size_t)BB * SS * DD;                  // [B, S, S]

    float *p_q, *p_kp, *p_vp, *p_op, *p_Wkp, *p_Wvp, *p_bkp, *p_bvp;
    cudaGetSymbolAddress((void**)&p_q,   g_q);
    cudaGetSymbolAddress((void**)&p_kp,  g_kp);
    cudaGetSymbolAddress((void**)&p_vp,  g_vp);
    cudaGetSymbolAddress((void**)&p_op,  g_outpre);
    cudaGetSymbolAddress((void**)&p_Wkp, g_Wkp);
    cudaGetSymbolAddress((void**)&p_Wvp, g_Wvp);
    cudaGetSymbolAddress((void**)&p_bkp, g_bkp);
    cudaGetSymbolAddress((void**)&p_bvp, g_bvp);

    const int M  = BB * SS;   // 32768
    const float scaling = 1.0f / sqrtf((float)DD);

    // 1) Fold projection matrices: Wkp = E1 @ Wk, Wvp = E2 @ Wv (512^3 each)
    {
        dim3 g(DD / 128, DD / 128, 1);
        sgemm_kernel<false><<<g, 256>>>(E1, Wk, p_Wkp, nullptr,
                                        DD, DD, DD, 1.0f, 0, 0, 0);
        sgemm_kernel<false><<<g, 256>>>(E2, Wv, p_Wvp, nullptr,
                                        DD, DD, DD, 1.0f, 0, 0, 0);
        fuse_bias_kernel<<<2, 256>>>(E1, bk, p_bkp);
        fuse_bias_kernel<<<2, 256>>>(E2, bv, p_bvp);
    }

    // 2) Input projections: q = q_in@Wq^T + bq ; kp = k_in@Wkp^T + bkp ; vp likewise
    {
        dim3 g(DD / 128, M / 128, 1);
        sgemm_kernel<true><<<g, 256>>>(q_in, Wq,    p_q,  bq,
                                       M, DD, DD, 1.0f, 0, 0, 0);
        sgemm_kernel<true><<<g, 256>>>(k_in, p_Wkp, p_kp, p_bkp,
                                       M, DD, DD, 1.0f, 0, 0, 0);
        sgemm_kernel<true><<<g, 256>>>(v_in, p_Wvp, p_vp, p_bvp,
                                       M, DD, DD, 1.0f, 0, 0, 0);
    }

    // 3) scores = scaling * q_b @ kp_b^T  -> written directly into attn region
    {
        dim3 g(SS / 128, SS / 128, BB);
        sgemm_kernel<true><<<g, 256>>>(p_q, p_kp, attn, nullptr,
                                       SS, SS, DD, scaling,
                                       (long long)SS * DD, (long long)SS * DD,
                                       (long long)SS * SS);
    }

    // 4) softmax rows, in place (this IS the attn output)
    softmax2048_kernel<<<BB * SS, 256>>>(attn);

    // 5) out_pre = attn_b @ vp_b
    {
        dim3 g(DD / 128, SS / 128, BB);
        sgemm_kernel<false><<<g, 256>>>(attn, p_vp, p_op, nullptr,
                                        SS, DD, SS, 1.0f,
                                        (long long)SS * SS, (long long)SS * DD,
                                        (long long)SS * DD);
    }

    // 6) out = out_pre @ Wo^T + bo
    {
        dim3 g(DD / 128, M / 128, 1);
        sgemm_kernel<true><<<g, 256>>>(p_op, Wo, outp, bo,
                                       M, DD, DD, 1.0f, 0, 0, 0);
    }
}

// round 3
// speedup vs baseline: 3.0630x; 3.0630x over previous
#include <cuda_runtime.h>
#include <cuda_bf16.h>
#include <math.h>
#include <stdint.h>

#define BB 16
#define SS 2048
#define DD 512
typedef __nv_bfloat16 bf16;
static const long long BSD = (long long)BB * SS * DD;

// ---------------------------------------------------------------------------
// Scratch (device globals — no allocation allowed)
// ---------------------------------------------------------------------------
__device__ float g_Wkp[DD * DD];
__device__ float g_Wvp[DD * DD];
__device__ float g_bkp[DD];
__device__ float g_bvp[DD];
__device__ float g_vp[(size_t)BB * SS * DD];

__device__ bf16 g_inq_hi[(size_t)BB * SS * DD], g_inq_lo[(size_t)BB * SS * DD];
__device__ bf16 g_ink_hi[(size_t)BB * SS * DD], g_ink_lo[(size_t)BB * SS * DD];
__device__ bf16 g_inv_hi[(size_t)BB * SS * DD], g_inv_lo[(size_t)BB * SS * DD];
__device__ bf16 g_Wq_hi[DD * DD],  g_Wq_lo[DD * DD];
__device__ bf16 g_Wkp_hi[DD * DD], g_Wkp_lo[DD * DD];
__device__ bf16 g_Wvp_hi[DD * DD], g_Wvp_lo[DD * DD];
__device__ bf16 g_Wo_hi[DD * DD],  g_Wo_lo[DD * DD];
__device__ bf16 g_q_hi[(size_t)BB * SS * DD],  g_q_lo[(size_t)BB * SS * DD];
__device__ bf16 g_kp_hi[(size_t)BB * SS * DD], g_kp_lo[(size_t)BB * SS * DD];
__device__ bf16 g_vpT_hi[(size_t)BB * SS * DD], g_vpT_lo[(size_t)BB * SS * DD];
__device__ bf16 g_attn_hi[(size_t)BB * SS * SS], g_attn_lo[(size_t)BB * SS * SS];
__device__ bf16 g_op_hi[(size_t)BB * SS * DD],  g_op_lo[(size_t)BB * SS * DD];

// ---------------------------------------------------------------------------
// helpers (portable sm_80+ feature set only: cp.async / ldmatrix / mma.sync)
// ---------------------------------------------------------------------------
__device__ __forceinline__ uint32_t smem_u32(const void* p) {
    uint32_t a;
    asm("{ .reg .u64 t; cvta.to.shared.u64 t, %1; cvt.u32.u64 %0, t; }"
        : "=r"(a) : "l"(p));
    return a;
}
__device__ __forceinline__ void cp_async16(uint32_t dst, const void* src) {
    asm volatile("cp.async.cg.shared.global [%0], [%1], 16;"
                 :: "r"(dst), "l"(src) : "memory");
}
__device__ __forceinline__ void cp_commit() {
    asm volatile("cp.async.commit_group;" ::: "memory");
}
__device__ __forceinline__ void cp_wait1() {
    asm volatile("cp.async.wait_group 1;" ::: "memory");
}
__device__ __forceinline__ void cp_wait0() {
    asm volatile("cp.async.wait_group 0;" ::: "memory");
}
__device__ __forceinline__ void ldsm4(uint32_t r[4], uint32_t addr) {
    asm volatile("ldmatrix.sync.aligned.m8n8.x4.shared.b16 {%0,%1,%2,%3}, [%4];"
                 : "=r"(r[0]), "=r"(r[1]), "=r"(r[2]), "=r"(r[3]) : "r"(addr));
}
__device__ __forceinline__ void mma16816(float c[4], const uint32_t a[4],
                                         uint32_t b0, uint32_t b1) {
    asm volatile(
        "mma.sync.aligned.m16n8k16.row.col.f32.bf16.bf16.f32 "
        "{%0,%1,%2,%3}, {%4,%5,%6,%7}, {%8,%9}, {%0,%1,%2,%3};"
        : "+f"(c[0]), "+f"(c[1]), "+f"(c[2]), "+f"(c[3])
        : "r"(a[0]), "r"(a[1]), "r"(a[2]), "r"(a[3]), "r"(b0), "r"(b1));
}

// ---------------------------------------------------------------------------
// bf16x3 tensor GEMM via mma.sync: C[m,n] = alpha*sum_k A[m,k]*B[n,k] (+bias)
// CTA tile 128x128, BK=32, 8 warps (warp tile 64x32), cp.async double buffer.
// M%128==0, N%128==0, K%32==0. Batched via blockIdx.z.
// SMEM stage (32KB): Ah[8K] Al[8K] Bh[8K] Bl[8K]; 2 stages = 64KB.
// Tile layout: row*64B + 16B*(k16 ^ ((row>>1)&3))  (conflict-free for LDSM+STS)
// ---------------------------------------------------------------------------
#define TG_THREADS 256
#define TG_STAGE   32768
#define TG_EPI     (128 * 136 * 4)     // 69632
#define TG_SMEM    TG_EPI

__global__ __launch_bounds__(TG_THREADS)
void tgemm_kernel(const bf16* __restrict__ Ahi, const bf16* __restrict__ Alo,
                  const bf16* __restrict__ Bhi, const bf16* __restrict__ Blo,
                  float* outF, bf16* outHi, bf16* outLo,
                  const float* __restrict__ bias,
                  int M, int N, int K, float alpha,
                  long long sA, long long sB, long long sC)
{
    extern __shared__ char smem[];
    const uint32_t sb = smem_u32(smem);
    const int tid  = threadIdx.x;
    const int lane = tid & 31;
    const int wid  = tid >> 5;
    const int wm   = wid & 1;       // 2 warp rows
    const int wn   = wid >> 1;      // 4 warp cols
    const int m0   = wm * 64;
    const int n0   = wn * 32;

    const long long bz = blockIdx.z;
    Ahi += bz * sA; Alo += bz * sA;
    Bhi += bz * sB; Blo += bz * sB;
    if (outF)  outF  += bz * sC;
    if (outHi) { outHi += bz * sC; outLo += bz * sC; }

    const int rowBase = blockIdx.y * 128;
    const int colBase = blockIdx.x * 128;

    // ---- per-thread cp.async geometry (2 chunks of 16B per tile) ----
    int   ldRow[2], ldK16[2];
    uint32_t ldOff[2];
#pragma unroll
    for (int i = 0; i < 2; i++) {
        int chunk = tid + i * 256;          // 0..511
        ldRow[i] = chunk >> 2;
        ldK16[i] = chunk & 3;
        ldOff[i] = (uint32_t)(ldRow[i] * 64 +
                   ((ldK16[i] ^ ((ldRow[i] >> 1) & 3)) * 16));
    }

    // ---- per-thread ldmatrix offsets (within stage, relative to tile base) ----
    uint32_t aoff[4][2], boff[2][2];
#pragma unroll
    for (int i = 0; i < 4; i++)
#pragma unroll
        for (int ks = 0; ks < 2; ks++) {
            int r = m0 + i * 16 + (lane & 7) + ((lane >> 3) & 1) * 8;
            int ch = ks * 2 + (lane >> 4);
            aoff[i][ks] = (uint32_t)(r * 64 + ((ch ^ ((r >> 1) & 3)) * 16));
        }
#pragma unroll
    for (int j = 0; j < 2; j++)
#pragma unroll
        for (int ks = 0; ks < 2; ks++) {
            int r = n0 + j * 16 + (lane & 7) + ((lane >> 4) & 1) * 8;
            int ch = ks * 2 + ((lane >> 3) & 1);
            boff[j][ks] = (uint32_t)(r * 64 + ((ch ^ ((r >> 1) & 3)) * 16));
        }

    float c[4][4][4];
#pragma unroll
    for (int i = 0; i < 4; i++)
#pragma unroll
        for (int j = 0; j < 4; j++)
#pragma unroll
            for (int e = 0; e < 4; e++) c[i][j][e] = 0.0f;

    const int nc = K >> 5;

    // issue loads for one stage
    auto load_stage = [&](int cidx) {
        const uint32_t dst = sb + (uint32_t)(cidx & 1) * TG_STAGE;
        const long long kb = (long long)cidx * 32;
#pragma unroll
        for (int i = 0; i < 2; i++) {
            const long long ea = (long long)(rowBase + ldRow[i]) * K + kb + ldK16[i] * 8;
            const long long eb = (long long)(colBase + ldRow[i]) * K + kb + ldK16[i] * 8;
            cp_async16(dst +         ldOff[i], Ahi + ea);
            cp_async16(dst +  8192 + ldOff[i], Alo + ea);
            cp_async16(dst + 16384 + ldOff[i], Bhi + eb);
            cp_async16(dst + 24576 + ldOff[i], Blo + eb);
        }
        cp_commit();
    };

    load_stage(0);

    for (int cidx = 0; cidx < nc; cidx++) {
        if (cidx + 1 < nc) { load_stage(cidx + 1); cp_wait1(); }
        else               { cp_wait0(); }
        __syncthreads();

        const uint32_t st = sb + (uint32_t)(cidx & 1) * TG_STAGE;
#pragma unroll
        for (int ks = 0; ks < 2; ks++) {
            uint32_t a[4][4], bh[2][4], bl[2][4];
#pragma unroll
            for (int i = 0; i < 4; i++) ldsm4(a[i], st + aoff[i][ks]);          // Ah
#pragma unroll
            for (int j = 0; j < 2; j++) ldsm4(bh[j], st + 16384 + boff[j][ks]); // Bh
#pragma unroll
            for (int j = 0; j < 2; j++) ldsm4(bl[j], st + 24576 + boff[j][ks]); // Bl
            // Ah*Bh and Ah*Bl
#pragma unroll
            for (int i = 0; i < 4; i++)
#pragma unroll
                for (int j = 0; j < 4; j++) {
                    mma16816(c[i][j], a[i], bh[j >> 1][(j & 1) * 2], bh[j >> 1][(j & 1) * 2 + 1]);
                    mma16816(c[i][j], a[i], bl[j >> 1][(j & 1) * 2], bl[j >> 1][(j & 1) * 2 + 1]);
                }
            // Al*Bh
#pragma unroll
            for (int i = 0; i < 4; i++) ldsm4(a[i], st + 8192 + aoff[i][ks]);   // Al
#pragma unroll
            for (int i = 0; i < 4; i++)
#pragma unroll
                for (int j = 0; j < 4; j++)
                    mma16816(c[i][j], a[i], bh[j >> 1][(j & 1) * 2], bh[j >> 1][(j & 1) * 2 + 1]);
        }
        __syncthreads();
    }

    // ---- epilogue: regs -> SMEM (pitch 136 floats) -> coalesced gmem ----
    float* sf = (float*)smem;
#pragma unroll
    for (int i = 0; i < 4; i++) {
        const int r = m0 + i * 16 + (lane >> 2);
#pragma unroll
        for (int j = 0; j < 4; j++) {
            const int cc = n0 + j * 8 + (lane & 3) * 2;
            sf[r * 136 + cc]           = c[i][j][0];
            sf[r * 136 + cc + 1]       = c[i][j][1];
            sf[(r + 8) * 136 + cc]     = c[i][j][2];
            sf[(r + 8) * 136 + cc + 1] = c[i][j][3];
        }
    }
    __syncthreads();
#pragma unroll 4
    for (int e = tid; e < 128 * 128; e += TG_THREADS) {
        const int r = e >> 7, cc = e & 127;
        float v = sf[r * 136 + cc] * alpha;
        const int gc = colBase + cc;
        if (bias) v += bias[gc];
        const long long gi = (long long)(rowBase + r) * N + gc;
        if (outF) outF[gi] = v;
        if (outHi) {
            bf16 h = __float2bfloat16_rn(v);
            outHi[gi] = h;
            outLo[gi] = __float2bfloat16_rn(v - __bfloat162float(h));
        }
    }
}

// ---------------------------------------------------------------------------
// fp32 SGEMM (small 512^3 fold GEMMs only): C = A @ B
// ---------------------------------------------------------------------------
__global__ __launch_bounds__(256)
void sgemm_nn_kernel(const float* __restrict__ A, const float* __restrict__ Bm,
                     float* __restrict__ C, int M, int N, int K)
{
    const int BK = 8;
    __shared__ float As[BK][128];
    __shared__ float Bs[BK][128];
    const int tid = threadIdx.x;
    const int tx = tid & 15, ty = tid >> 4;
    const int rowBase = blockIdx.y * 128, colBase = blockIdx.x * 128;
    float acc[8][8];
#pragma unroll
    for (int i = 0; i < 8; i++)
#pragma unroll
        for (int j = 0; j < 8; j++) acc[i][j] = 0.0f;

    for (int k0 = 0; k0 < K; k0 += BK) {
        {
            const int r = tid >> 1, kc = (tid & 1) * 4;
            float4 a = *reinterpret_cast<const float4*>(A + (long long)(rowBase + r) * K + k0 + kc);
            As[kc + 0][r] = a.x; As[kc + 1][r] = a.y; As[kc + 2][r] = a.z; As[kc + 3][r] = a.w;
        }
        {
            const int kr = tid >> 5, ccc = (tid & 31) * 4;
            float4 b = *reinterpret_cast<const float4*>(Bm + (long long)(k0 + kr) * N + colBase + ccc);
            Bs[kr][ccc + 0] = b.x; Bs[kr][ccc + 1] = b.y; Bs[kr][ccc + 2] = b.z; Bs[kr][ccc + 3] = b.w;
        }
        __syncthreads();
#pragma unroll
        for (int k = 0; k < BK; k++) {
            float4 a0 = *reinterpret_cast<const float4*>(&As[k][ty * 8]);
            float4 a1 = *reinterpret_cast<const float4*>(&As[k][ty * 8 + 4]);
            float4 b0 = *reinterpret_cast<const float4*>(&Bs[k][tx * 8]);
            float4 b1 = *reinterpret_cast<const float4*>(&Bs[k][tx * 8 + 4]);
            float ar[8] = {a0.x, a0.y, a0.z, a0.w, a1.x, a1.y, a1.z, a1.w};
            float br[8] = {b0.x, b0.y, b0.z, b0.w, b1.x, b1.y, b1.z, b1.w};
#pragma unroll
            for (int i = 0; i < 8; i++)
#pragma unroll
                for (int j = 0; j < 8; j++) acc[i][j] = fmaf(ar[i], br[j], acc[i][j]);
        }
        __syncthreads();
    }
#pragma unroll
    for (int i = 0; i < 8; i++) {
        const int r = rowBase + ty * 8 + i;
#pragma unroll
        for (int j = 0; j < 8; j += 4) {
            const int cc = colBase + tx * 8 + j;
            float4 v = {acc[i][j], acc[i][j + 1], acc[i][j + 2], acc[i][j + 3]};
            *reinterpret_cast<float4*>(C + (long long)r * N + cc) = v;
        }
    }
}

__global__ void fuse_bias_kernel(const float* __restrict__ E,
                                 const float* __restrict__ b,
                                 float* __restrict__ out)
{
    __shared__ float red[8];
    const int p = blockIdx.x;
    float s = 0.0f;
    for (int d = threadIdx.x; d < DD; d += 256)
        s = fmaf(E[(long long)p * DD + d], b[d], s);
#pragma unroll
    for (int o = 16; o > 0; o >>= 1) s += __shfl_xor_sync(0xffffffffu, s, o);
    if ((threadIdx.x & 31) == 0) red[threadIdx.x >> 5] = s;
    __syncthreads();
    if (threadIdx.x == 0) {
        float t = 0.0f;
#pragma unroll
        for (int i = 0; i < 8; i++) t += red[i];
        out[p] = t;
    }
}

__global__ void split_kernel(const float* __restrict__ x,
                             bf16* __restrict__ hi, bf16* __restrict__ lo,
                             long long n)
{
    long long i = (long long)blockIdx.x * blockDim.x + threadIdx.x;
    const long long stride = (long long)gridDim.x * blockDim.x;
    for (; i < n; i += stride) {
        float v = x[i];
        bf16 h = __float2bfloat16_rn(v);
        hi[i] = h;
        lo[i] = __float2bfloat16_rn(v - __bfloat162float(h));
    }
}

__global__ __launch_bounds__(256)
void softmax2048_kernel(float* __restrict__ data,
                        bf16* __restrict__ ohi, bf16* __restrict__ olo)
{
    const size_t base = (size_t)blockIdx.x * 2048;
    float* row = data + base;
    const int tid = threadIdx.x;
    __shared__ float red[8];

    float v[8];
    float m = -3.4e38f;
#pragma unroll
    for (int i = 0; i < 8; i++) { v[i] = row[tid + 256 * i]; m = fmaxf(m, v[i]); }
#pragma unroll
    for (int o = 16; o > 0; o >>= 1) m = fmaxf(m, __shfl_xor_sync(0xffffffffu, m, o));
    if ((tid & 31) == 0) red[tid >> 5] = m;
    __syncthreads();
    float bm = red[0];
#pragma unroll
    for (int i = 1; i < 8; i++) bm = fmaxf(bm, red[i]);
    __syncthreads();

    float s = 0.0f;
#pragma unroll
    for (int i = 0; i < 8; i++) { v[i] = __expf(v[i] - bm); s += v[i]; }
#pragma unroll
    for (int o = 16; o > 0; o >>= 1) s += __shfl_xor_sync(0xffffffffu, s, o);
    if ((tid & 31) == 0) red[tid >> 5] = s;
    __syncthreads();
    float bs = 0.0f;
#pragma unroll
    for (int i = 0; i < 8; i++) bs += red[i];

    const float inv = 1.0f / bs;
#pragma unroll
    for (int i = 0; i < 8; i++) {
        float r = v[i] * inv;
        const size_t idx = base + tid + 256 * i;
        data[idx] = r;
        bf16 h = __float2bfloat16_rn(r);
        ohi[idx] = h;
        olo[idx] = __float2bfloat16_rn(r - __bfloat162float(h));
    }
}

__global__ void transpose_split_kernel(const float* __restrict__ in,
                                       bf16* __restrict__ oh, bf16* __restrict__ ol)
{
    __shared__ float t[32][33];
    const float* src = in + (size_t)blockIdx.z * SS * DD;
    bf16* dh = oh + (size_t)blockIdx.z * SS * DD;
    bf16* dl = ol + (size_t)blockIdx.z * SS * DD;
    const int p0 = blockIdx.x * 32, t0 = blockIdx.y * 32;
#pragma unroll
    for (int i = 0; i < 32; i += 8)
        t[threadIdx.y + i][threadIdx.x] =
            src[(size_t)(t0 + threadIdx.y + i) * DD + p0 + threadIdx.x];
    __syncthreads();
#pragma unroll
    for (int i = 0; i < 32; i += 8) {
        float v = t[threadIdx.x][threadIdx.y + i];
        size_t o = (size_t)(p0 + threadIdx.y + i) * SS + t0 + threadIdx.x;
        bf16 h = __float2bfloat16_rn(v);
        dh[o] = h;
        dl[o] = __float2bfloat16_rn(v - __bfloat162float(h));
    }
}

// ---------------------------------------------------------------------------
// Launch
// ---------------------------------------------------------------------------
extern "C" void kernel_launch(void* const* d_in, const int* in_sizes, int n_in,
                              void* d_out, int out_size)
{
    const float* q_in = (const float*)d_in[0];
    const float* k_in = (const float*)d_in[1];
    const float* v_in = (const float*)d_in[2];
    const float* Wq   = (const float*)d_in[3];
    const float* bq   = (const float*)d_in[4];
    const float* Wk   = (const float*)d_in[5];
    const float* bk   = (const float*)d_in[6];
    const float* Wv   = (const float*)d_in[7];
    const float* bv   = (const float*)d_in[8];
    const float* E1   = (const float*)d_in[9];
    const float* E2   = (const float*)d_in[10];
    const float* Wo   = (const float*)d_in[11];
    const float* bo   = (const float*)d_in[12];

    float* outp = (float*)d_out;
    float* attn = outp + (size_t)BB * SS * DD;

    float *p_Wkp, *p_Wvp, *p_bkp, *p_bvp, *p_vp;
    cudaGetSymbolAddress((void**)&p_Wkp, g_Wkp);
    cudaGetSymbolAddress((void**)&p_Wvp, g_Wvp);
    cudaGetSymbolAddress((void**)&p_bkp, g_bkp);
    cudaGetSymbolAddress((void**)&p_bvp, g_bvp);
    cudaGetSymbolAddress((void**)&p_vp,  g_vp);
    bf16 *inq_h, *inq_l, *ink_h, *ink_l, *inv_h, *inv_l;
    bf16 *wq_h, *wq_l, *wkp_h, *wkp_l, *wvp_h, *wvp_l, *wo_h, *wo_l;
    bf16 *q_h, *q_l, *kp_h, *kp_l, *vpT_h, *vpT_l, *at_h, *at_l, *op_h, *op_l;
    cudaGetSymbolAddress((void**)&inq_h, g_inq_hi); cudaGetSymbolAddress((void**)&inq_l, g_inq_lo);
    cudaGetSymbolAddress((void**)&ink_h, g_ink_hi); cudaGetSymbolAddress((void**)&ink_l, g_ink_lo);
    cudaGetSymbolAddress((void**)&inv_h, g_inv_hi); cudaGetSymbolAddress((void**)&inv_l, g_inv_lo);
    cudaGetSymbolAddress((void**)&wq_h,  g_Wq_hi);  cudaGetSymbolAddress((void**)&wq_l,  g_Wq_lo);
    cudaGetSymbolAddress((void**)&wkp_h, g_Wkp_hi); cudaGetSymbolAddress((void**)&wkp_l, g_Wkp_lo);
    cudaGetSymbolAddress((void**)&wvp_h, g_Wvp_hi); cudaGetSymbolAddress((void**)&wvp_l, g_Wvp_lo);
    cudaGetSymbolAddress((void**)&wo_h,  g_Wo_hi);  cudaGetSymbolAddress((void**)&wo_l,  g_Wo_lo);
    cudaGetSymbolAddress((void**)&q_h,   g_q_hi);   cudaGetSymbolAddress((void**)&q_l,   g_q_lo);
    cudaGetSymbolAddress((void**)&kp_h,  g_kp_hi);  cudaGetSymbolAddress((void**)&kp_l,  g_kp_lo);
    cudaGetSymbolAddress((void**)&vpT_h, g_vpT_hi); cudaGetSymbolAddress((void**)&vpT_l, g_vpT_lo);
    cudaGetSymbolAddress((void**)&at_h,  g_attn_hi);cudaGetSymbolAddress((void**)&at_l,  g_attn_lo);
    cudaGetSymbolAddress((void**)&op_h,  g_op_hi);  cudaGetSymbolAddress((void**)&op_l,  g_op_lo);

    cudaFuncSetAttribute(tgemm_kernel, cudaFuncAttributeMaxDynamicSharedMemorySize, TG_SMEM);

    const int M = BB * SS;
    const float scaling = 1.0f / sqrtf((float)DD);

    // 1) fold: Wkp = E1 @ Wk, Wvp = E2 @ Wv ; bkp = E1 @ bk, bvp = E2 @ bv
    {
        dim3 g(DD / 128, DD / 128, 1);
        sgemm_nn_kernel<<<g, 256>>>(E1, Wk, p_Wkp, DD, DD, DD);
        sgemm_nn_kernel<<<g, 256>>>(E2, Wv, p_Wvp, DD, DD, DD);
        fuse_bias_kernel<<<DD, 256>>>(E1, bk, p_bkp);
        fuse_bias_kernel<<<DD, 256>>>(E2, bv, p_bvp);
    }

    // 2) split inputs + weights to hi/lo bf16
    split_kernel<<<2048, 256>>>(q_in, inq_h, inq_l, BSD);
    split_kernel<<<2048, 256>>>(k_in, ink_h, ink_l, BSD);
    split_kernel<<<2048, 256>>>(v_in, inv_h, inv_l, BSD);
    split_kernel<<<256, 256>>>(Wq,    wq_h,  wq_l,  (long long)DD * DD);
    split_kernel<<<256, 256>>>(p_Wkp, wkp_h, wkp_l, (long long)DD * DD);
    split_kernel<<<256, 256>>>(p_Wvp, wvp_h, wvp_l, (long long)DD * DD);
    split_kernel<<<256, 256>>>(Wo,    wo_h,  wo_l,  (long long)DD * DD);

    // 3) projections
    {
        dim3 g(DD / 128, M / 128, 1);
        tgemm_kernel<<<g, TG_THREADS, TG_SMEM>>>(inq_h, inq_l, wq_h, wq_l,
            nullptr, q_h, q_l, bq, M, DD, DD, 1.0f, 0, 0, 0);
        tgemm_kernel<<<g, TG_THREADS, TG_SMEM>>>(ink_h, ink_l, wkp_h, wkp_l,
            nullptr, kp_h, kp_l, p_bkp, M, DD, DD, 1.0f, 0, 0, 0);
        tgemm_kernel<<<g, TG_THREADS, TG_SMEM>>>(inv_h, inv_l, wvp_h, wvp_l,
            p_vp, nullptr, nullptr, p_bvp, M, DD, DD, 1.0f, 0, 0, 0);
    }

    // 4) vp -> vpT hi/lo
    transpose_split_kernel<<<dim3(DD / 32, SS / 32, BB), dim3(32, 8)>>>(p_vp, vpT_h, vpT_l);

    // 5) scores = scaling * q @ kp^T -> attn region fp32
    tgemm_kernel<<<dim3(SS / 128, SS / 128, BB), TG_THREADS, TG_SMEM>>>(
        q_h, q_l, kp_h, kp_l, attn, nullptr, nullptr, nullptr,
        SS, SS, DD, scaling,
        (long long)SS * DD, (long long)SS * DD, (long long)SS * SS);

    // 6) softmax in place + hi/lo
    softmax2048_kernel<<<BB * SS, 256>>>(attn, at_h, at_l);

    // 7) op = attn @ vpT^T (K = 2048)
    tgemm_kernel<<<dim3(DD / 128, SS / 128, BB), TG_THREADS, TG_SMEM>>>(
        at_h, at_l, vpT_h, vpT_l, nullptr, op_h, op_l, nullptr,
        SS, DD, SS, 1.0f,
        (long long)SS * SS, (long long)SS * DD, (long long)SS * DD);

    // 8) out = op @ Wo^T + bo
    tgemm_kernel<<<dim3(DD / 128, M / 128, 1), TG_THREADS, TG_SMEM>>>(
        op_h, op_l, wo_h, wo_l, outp, nullptr, nullptr, bo,
        M, DD, DD, 1.0f, 0, 0, 0);
}